// round 2
// baseline (speedup 1.0000x reference)
#include <cuda_runtime.h>
#include <cstdint>

// BatchBlur: per-pixel 19x19 blur, reflection pad, weights shared across C=3.
//   input : (2, 3, 256, 256) f32
//   kernel: (2, 65536, 19, 19) f32   (189 MB streamed once -> DRAM floor ~29us)
//   out   : (2, 3, 256, 256) f32 = sum(patch*w)/361
//
// Design: 16 pixels per 128-thread block (8x2 tile), 8 sub-threads per pixel.
//  - weights cp.async-staged into smem, pixel-major stride 376 (conflict-free LDS)
//  - planar input patch in smem (3 x 20x26)
//  - sub-thread handles taps sub+8j (unrolled), 3-step shuffle reduce over subs

#define Hh 256
#define Ww 256
#define HW 65536
#define K2 361
#define TPB 128
#define NPIX 16           // 8 wide x 2 tall
#define WSTRIDE 376       // 361 padded; 376 % 32 == 24 -> bank-conflict-free
#define PROWS 20          // 2 + 18
#define PCOLS 26          // 8 + 18
#define PLANE 520         // PROWS * PCOLS
#define WELEMS (NPIX * K2)      // 5776
#define PELEMS (3 * PLANE)      // 1560

__device__ __forceinline__ uint32_t smem_u32(const void* p) {
    uint32_t a;
    asm("{ .reg .u64 t; cvta.to.shared.u64 t, %1; cvt.u32.u64 %0, t; }"
        : "=r"(a) : "l"(p));
    return a;
}

__device__ __forceinline__ int reflect_h(int v) {
    return (v < 0) ? -v : ((v >= Hh) ? (2 * Hh - 2 - v) : v);
}

__global__ __launch_bounds__(TPB)
void batchblur_kernel(const float* __restrict__ inp,
                      const float* __restrict__ kw,
                      float* __restrict__ out)
{
    __shared__ float sw[NPIX * WSTRIDE];   // 23.5 KB
    __shared__ float sp[PELEMS];           // 6.24 KB, planar

    const int tid = threadIdx.x;
    const int blk = blockIdx.x;
    const int b   = blk >> 12;             // 4096 tiles per batch
    const int t   = blk & 4095;
    const int y0  = (t >> 5) << 1;         // tile top row   (2 rows/tile)
    const int x0  = (t & 31) << 3;         // tile left col  (8 cols/tile)

    // ---- stage input patch (planar, reflected), rows [y0-9, y0+10], cols [x0-9, x0+16]
    const float* inb = inp + (size_t)b * (3 * HW);
    #pragma unroll 4
    for (int i = tid; i < PELEMS; i += TPB) {
        int c   = i / PLANE;
        int r2  = i - c * PLANE;
        int r   = r2 / PCOLS;
        int col = r2 - r * PCOLS;
        int y = reflect_h(y0 + r - 9);
        int x = reflect_h(x0 + col - 9);
        sp[i] = __ldg(inb + c * HW + y * Ww + x);
    }

    // ---- stage weights via cp.async (4B), linear gmem -> padded pixel-major smem
    const uint32_t sw_base = smem_u32(sw);
    const size_t   bp      = (size_t)b * HW;
    #pragma unroll 4
    for (int i = tid; i < WELEMS; i += TPB) {
        int p   = i / K2;                   // local pixel 0..15
        int tap = i - p * K2;
        int gp  = (y0 + (p >> 3)) * Ww + x0 + (p & 7);
        const float* src = kw + (bp + (size_t)gp) * K2 + tap;
        uint32_t dst = sw_base + (uint32_t)(p * WSTRIDE + tap) * 4u;
        asm volatile("cp.async.ca.shared.global [%0], [%1], 4;"
                     :: "r"(dst), "l"(src));
    }
    asm volatile("cp.async.commit_group;");
    asm volatile("cp.async.wait_group 0;" ::: "memory");
    __syncthreads();

    // ---- compute: pixel pl = tid>>3, sub-thread sub = tid&7 covers taps sub+8j
    const int pl  = tid >> 3;
    const int sub = tid & 7;
    const int tx  = pl & 7;
    const int tyl = pl >> 3;

    const float* wp = sw + pl * WSTRIDE + sub;
    int pos = tyl * PCOLS + tx + sub;      // (tyl+ki)*26 + tx + kj, ki=0 kj=sub
    int kj  = sub;

    float a0 = 0.f, a1 = 0.f, a2 = 0.f;
    #pragma unroll
    for (int j = 0; j < 45; j++) {
        float w = wp[j * 8];
        a0 += w * sp[pos];
        a1 += w * sp[PLANE + pos];
        a2 += w * sp[2 * PLANE + pos];
        // advance tap by 8: kj+=8 with row wrap (19 cols, patch stride 26)
        bool c = (kj >= 11);
        pos += c ? 15 : 8;                 // 8 + (26-19) on wrap
        kj  += c ? -11 : 8;
    }
    if (sub == 0) {                        // tap 360 = (18,18)
        float w = wp[360];
        int p3 = (tyl + 18) * PCOLS + tx + 18;
        a0 += w * sp[p3];
        a1 += w * sp[PLANE + p3];
        a2 += w * sp[2 * PLANE + p3];
    }

    // ---- reduce over 8 sub-threads (lanes pl*8+sub -> xor 1,2,4 stay in-group)
    #pragma unroll
    for (int m = 1; m <= 4; m <<= 1) {
        a0 += __shfl_xor_sync(0xffffffffu, a0, m);
        a1 += __shfl_xor_sync(0xffffffffu, a1, m);
        a2 += __shfl_xor_sync(0xffffffffu, a2, m);
    }

    if (sub == 0) {
        const float inv = 1.0f / 361.0f;
        int gp = (y0 + tyl) * Ww + x0 + tx;
        float* ob = out + (size_t)b * (3 * HW) + gp;
        ob[0]      = a0 * inv;
        ob[HW]     = a1 * inv;
        ob[2 * HW] = a2 * inv;
    }
}

extern "C" void kernel_launch(void* const* d_in, const int* in_sizes, int n_in,
                              void* d_out, int out_size)
{
    const float* inp = (const float*)d_in[0];
    const float* kw  = (const float*)d_in[1];
    if (n_in >= 2 && in_sizes[0] > in_sizes[1]) {   // identify big weight tensor
        inp = (const float*)d_in[1];
        kw  = (const float*)d_in[0];
    }
    const int grid = 2 * (Hh / 2) * (Ww / 8);       // 8192 blocks
    batchblur_kernel<<<grid, TPB>>>(inp, kw, (float*)d_out);
}

// round 3
// speedup vs baseline: 1.9811x; 1.9811x over previous
#include <cuda_runtime.h>
#include <cstdint>

// BatchBlur: per-pixel 19x19 blur, reflection pad, weights shared across C=3.
//   input : (2, 3, 256, 256) f32 (tiny, reused 361x -> smem patch)
//   kernel: (2, 65536, 19, 19) f32 (189 MB streamed ONCE -> gmem->reg direct)
//   out   : (2, 3, 256, 256) f32 = sum(patch*w)/361
//
// 256-thread block = 32 pixels (8x4 tile) x 8 sub-threads.
// Sub-thread s handles taps s+8j (j=0..44, +tap360 on s==0), weight loads are
// 32B-coalesced per pixel. Input patch lives in smem as channel-interleaved
// float4 [22 rows][26 cols] -> one LDS.128 per tap covers all 3 channels.

#define Hh 256
#define Ww 256
#define HW 65536
#define K2 361
#define TPB 256
#define TW 8              // tile width  (pixels)
#define TH 4              // tile height (pixels)
#define PR 22             // TH + 18
#define PC 26             // TW + 18
#define PLANE (PR * PC)   // 572 float4 slots

__device__ __forceinline__ int reflect_h(int v) {
    return (v < 0) ? -v : ((v >= Hh) ? (2 * Hh - 2 - v) : v);
}

__global__ __launch_bounds__(TPB)
void batchblur_kernel(const float* __restrict__ inp,
                      const float* __restrict__ kw,
                      float* __restrict__ out)
{
    __shared__ float4 s4[PLANE];          // 9.15 KB, [r][col].xyz = channels

    const int tid = threadIdx.x;
    const int blk = blockIdx.x;
    const int b   = blk >> 11;            // 2048 tiles per batch
    const int t   = blk & 2047;
    const int y0  = (t >> 5) << 2;        // tile top row (4 rows)
    const int x0  = (t & 31) << 3;        // tile left col (8 cols)

    // ---- stage reflected input patch, channel-interleaved float4
    {
        float* sf = (float*)s4;
        const float* inb = inp + (size_t)b * (3 * HW);
        #pragma unroll
        for (int c = 0; c < 3; c++) {
            for (int rc = tid; rc < PLANE; rc += TPB) {
                int r   = rc / PC;
                int col = rc - r * PC;
                int y = reflect_h(y0 + r - 9);
                int x = reflect_h(x0 + col - 9);
                sf[rc * 4 + c] = __ldg(inb + c * HW + y * Ww + x);
            }
        }
    }
    __syncthreads();

    // ---- compute: pixel pl = tid>>3, sub s = tid&7 handles taps s+8j
    const int pl  = tid >> 3;             // 0..31
    const int sub = tid & 7;
    const int tx  = pl & 7;
    const int ty  = pl >> 3;

    const int p = (y0 + ty) * Ww + (x0 + tx);                 // global pixel
    const float* wp = kw + ((size_t)b * HW + (size_t)p) * K2 + sub;

    int pos = ty * PC + tx + sub;         // (ty+ki)*26 + tx+kj, ki=0 kj=sub
    int kj  = sub;

    float a0 = 0.f, a1 = 0.f, a2 = 0.f;
    #pragma unroll
    for (int j = 0; j < 45; j++) {
        float  w = __ldcs(wp + j * 8);    // immediate offset, streaming
        float4 v = s4[pos];
        a0 += w * v.x;
        a1 += w * v.y;
        a2 += w * v.z;
        bool c = (kj >= 11);              // kj+8 >= 19 -> row wrap
        pos += c ? 15 : 8;                // 8 + (26-19) on wrap
        kj  += c ? -11 : 8;
    }
    if (sub == 0) {                       // tap 360 = (18,18)
        float  w = __ldcs(wp + 360);
        float4 v = s4[(ty + 18) * PC + tx + 18];
        a0 += w * v.x;
        a1 += w * v.y;
        a2 += w * v.z;
    }

    // ---- reduce over 8 sub-threads (xor 1,2,4 stays inside the 8-group)
    #pragma unroll
    for (int m = 1; m <= 4; m <<= 1) {
        a0 += __shfl_xor_sync(0xffffffffu, a0, m);
        a1 += __shfl_xor_sync(0xffffffffu, a1, m);
        a2 += __shfl_xor_sync(0xffffffffu, a2, m);
    }

    if (sub == 0) {
        const float inv = 1.0f / 361.0f;
        float* ob = out + (size_t)b * (3 * HW) + p;
        ob[0]      = a0 * inv;
        ob[HW]     = a1 * inv;
        ob[2 * HW] = a2 * inv;
    }
}

extern "C" void kernel_launch(void* const* d_in, const int* in_sizes, int n_in,
                              void* d_out, int out_size)
{
    const float* inp = (const float*)d_in[0];
    const float* kw  = (const float*)d_in[1];
    if (n_in >= 2 && in_sizes[0] > in_sizes[1]) {   // big tensor = weights
        inp = (const float*)d_in[1];
        kw  = (const float*)d_in[0];
    }
    const int grid = 2 * (Hh / TH) * (Ww / TW);     // 4096 blocks
    batchblur_kernel<<<grid, TPB>>>(inp, kw, (float*)d_out);
}

// round 6
// speedup vs baseline: 2.0520x; 1.0358x over previous
#include <cuda_runtime.h>
#include <cstdint>

// BatchBlur: per-pixel 19x19 blur, reflection pad, weights shared across C=3.
//   input : (2,3,256,256) f32 (361x reuse -> smem patch, float4 xyz=channels)
//   kernel: (2,65536,19,19) f32 (189MB streamed once, gmem->reg via __ldcs)
//   out   : (2,3,256,256) f32 = sum(patch*w)/361
//
// Thread owns 4 adjacent pixels (d=0..3): one input LDS.128 feeds 12 FMAs.
// Warp = 4 groups x 8 subs = 16 pixels of one row. Block = 8 warps = 16x8 tile.
// Sub s covers input-columns u = s+8*jj (jj=0..2); weight (ki,kj) of pixel d is
// read at u=kj+d -> unique (s,jj): each weight loaded exactly once, coalesced.
// ki loop kept ROLLED (body fits L0 I$; predicates/offsets hoisted).

#define Hh 256
#define Ww 256
#define HW 65536
#define K2 361
#define TPB 256
#define TILE_W 16
#define TILE_H 8
#define PRR 26            // TILE_H + 18
#define PCC 36            // TILE_W + 18 (+2 pad; max u=21)
#define NP4 (PRR * PCC)   // 936 float4 slots (~15 KB)

__device__ __forceinline__ int reflect_h(int v) {
    return (v < 0) ? -v : ((v >= Hh) ? (2 * Hh - 2 - v) : v);
}

__global__ __launch_bounds__(TPB)
void batchblur_kernel(const float* __restrict__ inp,
                      const float* __restrict__ kw,
                      float* __restrict__ out)
{
    __shared__ float4 s4[NP4];

    const int tid = threadIdx.x;
    const int blk = blockIdx.x;
    const int b   = blk >> 9;             // 512 tiles per batch
    const int t   = blk & 511;
    const int ty0 = (t >> 4) << 3;        // 32 row-tiles of height 8
    const int x0  = (t & 15) << 4;        // 16 col-tiles of width 16

    // ---- stage reflected patch: rows [ty0-9, ty0+16], cols [x0-9, x0+26]
    {
        const float* inb = inp + (size_t)b * (3 * HW);
        for (int i = tid; i < NP4; i += TPB) {
            int r = i / PCC;
            int c = i - r * PCC;
            int y = reflect_h(ty0 + r - 9);
            int x = reflect_h(x0 + c - 9);
            const float* q = inb + y * Ww + x;
            float4 v;
            v.x = __ldg(q);
            v.y = __ldg(q + HW);
            v.z = __ldg(q + 2 * HW);
            v.w = 0.f;
            s4[i] = v;
        }
    }
    __syncthreads();

    // ---- compute
    const int lane = tid & 31;
    const int wr   = tid >> 5;            // warp = tile row 0..7
    const int g    = lane >> 3;           // pixel group 0..3
    const int s    = lane & 7;            // sub-thread 0..7

    const int y  = ty0 + wr;
    const int px = x0 + (g << 2);         // first of 4 pixels
    const size_t p0 = (size_t)b * HW + (size_t)(y * Ww + px);
    const float* wb = kw + p0 * K2 + s;

    const float4* srow = s4 + wr * PCC + (g << 2);

    // Hoisted per-(jj,d) validity and constant weight offsets (ki-independent)
    bool  val[3][4];
    int   off[3][4];
    #pragma unroll
    for (int jj = 0; jj < 3; jj++) {
        const int u = s + 8 * jj;
        #pragma unroll
        for (int d = 0; d < 4; d++) {
            const int kj = u - d;
            val[jj][d] = (u <= 21) && (kj >= 0) && (kj <= 18);
            off[jj][d] = 8 * jj + d * 360;
        }
    }
    const bool uok0 = (s + 0  <= 21);     // always true
    const bool uok1 = (s + 8  <= 21);
    const bool uok2 = (s + 16 <= 21);

    float a00=0,a01=0,a02=0, a10=0,a11=0,a12=0;
    float a20=0,a21=0,a22=0, a30=0,a31=0,a32=0;

    #pragma unroll 1
    for (int ki = 0; ki < 19; ki++) {
        const float* wrow = wb + ki * 19;
        const float4* sr  = srow + ki * PCC;

        #pragma unroll
        for (int jj = 0; jj < 3; jj++) {
            const bool uok = (jj == 0) ? uok0 : (jj == 1) ? uok1 : uok2;
            if (uok) {
                const float4 v = sr[s + 8 * jj];
                #pragma unroll
                for (int d = 0; d < 4; d++) {
                    float w = 0.f;
                    if (val[jj][d]) w = __ldcs(wrow + off[jj][d]);
                    if (d == 0) { a00 += w*v.x; a01 += w*v.y; a02 += w*v.z; }
                    if (d == 1) { a10 += w*v.x; a11 += w*v.y; a12 += w*v.z; }
                    if (d == 2) { a20 += w*v.x; a21 += w*v.y; a22 += w*v.z; }
                    if (d == 3) { a30 += w*v.x; a31 += w*v.y; a32 += w*v.z; }
                }
            }
        }
    }

    // ---- reduce over the 8 sub-threads (xor 1,2,4 stays inside each group)
    #pragma unroll
    for (int m = 1; m <= 4; m <<= 1) {
        a00 += __shfl_xor_sync(0xffffffffu, a00, m);
        a01 += __shfl_xor_sync(0xffffffffu, a01, m);
        a02 += __shfl_xor_sync(0xffffffffu, a02, m);
        a10 += __shfl_xor_sync(0xffffffffu, a10, m);
        a11 += __shfl_xor_sync(0xffffffffu, a11, m);
        a12 += __shfl_xor_sync(0xffffffffu, a12, m);
        a20 += __shfl_xor_sync(0xffffffffu, a20, m);
        a21 += __shfl_xor_sync(0xffffffffu, a21, m);
        a22 += __shfl_xor_sync(0xffffffffu, a22, m);
        a30 += __shfl_xor_sync(0xffffffffu, a30, m);
        a31 += __shfl_xor_sync(0xffffffffu, a31, m);
        a32 += __shfl_xor_sync(0xffffffffu, a32, m);
    }

    if (s < 4) {                          // lane s writes pixel px+s
        float c0, c1, c2;
        if (s == 0) { c0=a00; c1=a01; c2=a02; }
        if (s == 1) { c0=a10; c1=a11; c2=a12; }
        if (s == 2) { c0=a20; c1=a21; c2=a22; }
        if (s == 3) { c0=a30; c1=a31; c2=a32; }
        const float inv = 1.0f / 361.0f;
        float* ob = out + (size_t)b * (3 * HW) + (y * Ww + px + s);
        ob[0]      = c0 * inv;
        ob[HW]     = c1 * inv;
        ob[2 * HW] = c2 * inv;
    }
}

extern "C" void kernel_launch(void* const* d_in, const int* in_sizes, int n_in,
                              void* d_out, int out_size)
{
    const float* inp = (const float*)d_in[0];
    const float* kw  = (const float*)d_in[1];
    if (n_in >= 2 && in_sizes[0] > in_sizes[1]) {   // big tensor = weights
        inp = (const float*)d_in[1];
        kw  = (const float*)d_in[0];
    }
    const int grid = 2 * (Hh / TILE_H) * (Ww / TILE_W);   // 1024 blocks
    batchblur_kernel<<<grid, TPB>>>(inp, kw, (float*)d_out);
}

// round 8
// speedup vs baseline: 2.4939x; 1.2154x over previous
#include <cuda_runtime.h>
#include <cstdint>

// BatchBlur: per-pixel 19x19 blur, reflection pad, weights shared across C=3.
//   input : (2,3,256,256) f32 (361x reuse -> smem patch, float4 xyz=channels)
//   kernel: (2,65536,19,19) f32 (189MB streamed once, gmem->reg via __ldcs)
//   out   : (2,3,256,256) f32 = sum(patch*w)/361
//
// Thread owns 4 adjacent pixels (d=0..3): one input LDS.128 feeds 12 FMAs.
// Warp = 4 groups x 8 subs = 16 pixels of one row. Block = 8 warps = 16x8 tile.
// Sub s covers input-columns u = s+8*jj; weight (ki,kj) of pixel d is read at
// u=kj+d -> unique (s,jj): each weight loaded exactly once, coalesced.
// R6 fix: SOFTWARE PIPELINE the weight loads (prefetch ki+1 while FMA-ing ki)
// to break the per-iteration load->use serialization (issue was 25%).

#define Hh 256
#define Ww 256
#define HW 65536
#define K2 361
#define TPB 256
#define TILE_W 16
#define TILE_H 8
#define PRR 26            // TILE_H + 18
#define PCC 36            // TILE_W + 18 (+2 pad; max u=21)
#define NP4 (PRR * PCC)   // 936 float4 slots (~15 KB)

__device__ __forceinline__ int reflect_h(int v) {
    return (v < 0) ? -v : ((v >= Hh) ? (2 * Hh - 2 - v) : v);
}

__global__ __launch_bounds__(TPB)
void batchblur_kernel(const float* __restrict__ inp,
                      const float* __restrict__ kw,
                      float* __restrict__ out)
{
    __shared__ float4 s4[NP4];

    const int tid = threadIdx.x;
    const int blk = blockIdx.x;
    const int b   = blk >> 9;             // 512 tiles per batch
    const int t   = blk & 511;
    const int ty0 = (t >> 4) << 3;        // 32 row-tiles of height 8
    const int x0  = (t & 15) << 4;        // 16 col-tiles of width 16

    // ---- stage reflected patch: rows [ty0-9, ty0+16], cols [x0-9, x0+26]
    {
        const float* inb = inp + (size_t)b * (3 * HW);
        for (int i = tid; i < NP4; i += TPB) {
            int r = i / PCC;
            int c = i - r * PCC;
            int y = reflect_h(ty0 + r - 9);
            int x = reflect_h(x0 + c - 9);
            const float* q = inb + y * Ww + x;
            float4 v;
            v.x = __ldg(q);
            v.y = __ldg(q + HW);
            v.z = __ldg(q + 2 * HW);
            v.w = 0.f;
            s4[i] = v;
        }
    }
    __syncthreads();

    // ---- compute
    const int lane = tid & 31;
    const int wr   = tid >> 5;            // warp = tile row 0..7
    const int g    = lane >> 3;           // pixel group 0..3
    const int s    = lane & 7;            // sub-thread 0..7

    const int y  = ty0 + wr;
    const int px = x0 + (g << 2);         // first of 4 pixels
    const size_t p0 = (size_t)b * HW + (size_t)(y * Ww + px);
    const float* wb = kw + p0 * K2 + s;

    const float4* srow = s4 + wr * PCC + (g << 2);

    // Hoisted per-(jj,d) validity (ki-independent)
    bool val[3][4];
    #pragma unroll
    for (int jj = 0; jj < 3; jj++) {
        const int u = s + 8 * jj;
        #pragma unroll
        for (int d = 0; d < 4; d++) {
            const int kj = u - d;
            val[jj][d] = (u <= 21) && (kj >= 0) && (kj <= 18);
        }
    }
    const bool uok1 = (s + 8  <= 21);
    const bool uok2 = (s + 16 <= 21);

    float a00=0,a01=0,a02=0, a10=0,a11=0,a12=0;
    float a20=0,a21=0,a22=0, a30=0,a31=0,a32=0;

    // ---- software-pipelined weight stream: prefetch ki+1 while consuming ki
    float wcur[12];
    #pragma unroll
    for (int jj = 0; jj < 3; jj++)
        #pragma unroll
        for (int d = 0; d < 4; d++)
            wcur[jj * 4 + d] = val[jj][d] ? __ldcs(wb + 8 * jj + d * 360) : 0.f;

    #pragma unroll 1
    for (int ki = 0; ki < 19; ki++) {
        float wnxt[12];
        const bool more = (ki < 18);
        const float* wrow = wb + (ki + 1) * 19;
        #pragma unroll
        for (int jj = 0; jj < 3; jj++)
            #pragma unroll
            for (int d = 0; d < 4; d++)
                wnxt[jj * 4 + d] = (more && val[jj][d])
                                 ? __ldcs(wrow + 8 * jj + d * 360) : 0.f;

        const float4* sr = srow + ki * PCC;
        {
            const float4 v = sr[s];
            a00 += wcur[0]*v.x; a01 += wcur[0]*v.y; a02 += wcur[0]*v.z;
            a10 += wcur[1]*v.x; a11 += wcur[1]*v.y; a12 += wcur[1]*v.z;
            a20 += wcur[2]*v.x; a21 += wcur[2]*v.y; a22 += wcur[2]*v.z;
            a30 += wcur[3]*v.x; a31 += wcur[3]*v.y; a32 += wcur[3]*v.z;
        }
        if (uok1) {
            const float4 v = sr[s + 8];
            a00 += wcur[4]*v.x; a01 += wcur[4]*v.y; a02 += wcur[4]*v.z;
            a10 += wcur[5]*v.x; a11 += wcur[5]*v.y; a12 += wcur[5]*v.z;
            a20 += wcur[6]*v.x; a21 += wcur[6]*v.y; a22 += wcur[6]*v.z;
            a30 += wcur[7]*v.x; a31 += wcur[7]*v.y; a32 += wcur[7]*v.z;
        }
        if (uok2) {
            const float4 v = sr[s + 16];
            a00 += wcur[8] *v.x; a01 += wcur[8] *v.y; a02 += wcur[8] *v.z;
            a10 += wcur[9] *v.x; a11 += wcur[9] *v.y; a12 += wcur[9] *v.z;
            a20 += wcur[10]*v.x; a21 += wcur[10]*v.y; a22 += wcur[10]*v.z;
            a30 += wcur[11]*v.x; a31 += wcur[11]*v.y; a32 += wcur[11]*v.z;
        }

        #pragma unroll
        for (int i = 0; i < 12; i++) wcur[i] = wnxt[i];
    }

    // ---- reduce over the 8 sub-threads (xor 1,2,4 stays inside each group)
    #pragma unroll
    for (int m = 1; m <= 4; m <<= 1) {
        a00 += __shfl_xor_sync(0xffffffffu, a00, m);
        a01 += __shfl_xor_sync(0xffffffffu, a01, m);
        a02 += __shfl_xor_sync(0xffffffffu, a02, m);
        a10 += __shfl_xor_sync(0xffffffffu, a10, m);
        a11 += __shfl_xor_sync(0xffffffffu, a11, m);
        a12 += __shfl_xor_sync(0xffffffffu, a12, m);
        a20 += __shfl_xor_sync(0xffffffffu, a20, m);
        a21 += __shfl_xor_sync(0xffffffffu, a21, m);
        a22 += __shfl_xor_sync(0xffffffffu, a22, m);
        a30 += __shfl_xor_sync(0xffffffffu, a30, m);
        a31 += __shfl_xor_sync(0xffffffffu, a31, m);
        a32 += __shfl_xor_sync(0xffffffffu, a32, m);
    }

    if (s < 4) {                          // lane s writes pixel px+s
        float c0, c1, c2;
        if (s == 0) { c0=a00; c1=a01; c2=a02; }
        if (s == 1) { c0=a10; c1=a11; c2=a12; }
        if (s == 2) { c0=a20; c1=a21; c2=a22; }
        if (s == 3) { c0=a30; c1=a31; c2=a32; }
        const float inv = 1.0f / 361.0f;
        float* ob = out + (size_t)b * (3 * HW) + (y * Ww + px + s);
        ob[0]      = c0 * inv;
        ob[HW]     = c1 * inv;
        ob[2 * HW] = c2 * inv;
    }
}

extern "C" void kernel_launch(void* const* d_in, const int* in_sizes, int n_in,
                              void* d_out, int out_size)
{
    const float* inp = (const float*)d_in[0];
    const float* kw  = (const float*)d_in[1];
    if (n_in >= 2 && in_sizes[0] > in_sizes[1]) {   // big tensor = weights
        inp = (const float*)d_in[1];
        kw  = (const float*)d_in[0];
    }
    const int grid = 2 * (Hh / TILE_H) * (Ww / TILE_W);   // 1024 blocks
    batchblur_kernel<<<grid, TPB>>>(inp, kw, (float*)d_out);
}